// round 13
// baseline (speedup 1.0000x reference)
#include <cuda_runtime.h>
#include <cuda_bf16.h>
#include <cstdint>

#define NUM_NODES 20000
#define SEQ_LEN 128
#define HIDDEN 32
#define N_TOTAL (NUM_NODES * SEQ_LEN)        // 2,560,000
#define N_EDGES 2000000

__device__ float g_agg2[(size_t)N_TOTAL * 2];
__device__ float g_deg[N_TOTAL];
// x_proj[t][row][node], row = gate*32+u  (1.31 GB)
__device__ float g_xproj[(size_t)SEQ_LEN * 128 * NUM_NODES];

typedef unsigned long long ull;

__device__ __forceinline__ ull ffma2(ull a, ull b, ull c) {
    ull d;
    asm("fma.rn.f32x2 %0, %1, %2, %3;" : "=l"(d) : "l"(a), "l"(b), "l"(c));
    return d;
}
__device__ __forceinline__ ull pk(float lo, float hi) {
    ull r;
    asm("mov.b64 %0, {%1, %2};" : "=l"(r) : "f"(lo), "f"(hi));
    return r;
}
__device__ __forceinline__ float2 upk(ull v) {
    float2 r;
    asm("mov.b64 {%0, %1}, %2;" : "=f"(r.x), "=f"(r.y) : "l"(v));
    return r;
}
__device__ __forceinline__ float tanh_hw(float v) {
    float r;
    asm("tanh.approx.f32 %0, %1;" : "=f"(r) : "f"(v));
    return r;
}
__device__ __forceinline__ float sigmoid_hw(float v) {
    return fmaf(0.5f, tanh_hw(0.5f * v), 0.5f);
}

// ---------------------------------------------------------------------------
// GCN kernels (edge_index arrives as int32)
// ---------------------------------------------------------------------------

__global__ void deg_kernel(const int* __restrict__ ei, float* __restrict__ deg) {
    int e = blockIdx.x * blockDim.x + threadIdx.x;
    if (e < N_EDGES) {
        int dst = ei[N_EDGES + e];
        atomicAdd(deg + dst, 1.0f);
    }
}

__global__ void dinv_kernel(float* __restrict__ deg) {
    int i = blockIdx.x * blockDim.x + threadIdx.x;
    if (i < N_TOTAL) {
        deg[i] = rsqrtf(deg[i] + 1.0f);
    }
}

__global__ void edge_scatter2(const int* __restrict__ ei,
                              const float* __restrict__ x,
                              const float* __restrict__ dinv,
                              float* __restrict__ agg2) {
    int e = blockIdx.x * blockDim.x + threadIdx.x;
    if (e >= N_EDGES) return;
    int src = ei[e];
    int dst = ei[N_EDGES + e];
    float norm = dinv[src] * dinv[dst];
    float2 xv = *(const float2*)(x + 2 * (size_t)src);
    float* p = agg2 + 2 * (size_t)dst;
    atomicAdd(p, xv.x * norm);
    atomicAdd(p + 1, xv.y * norm);
}

// ---------------------------------------------------------------------------
// x_proj kernel: x_proj[t][row][node] = dot(relu(gcn(x)), w_ih[row]) + bias[row]
// Block = 128 threads handles 32 nodes, all t. Thread r owns w_ih row r in
// registers (no broadcast-LDS tax). Phase A: 128 threads compute the 32-node
// x_gcn tile into SMEM. Phase B: thread r computes row r for all 32 nodes and
// writes one contiguous 128B chunk per 4 nodes (coalesced, node fastest dim).
// ---------------------------------------------------------------------------

#define XP_TPB 128
#define XG_PITCH 36   // 144B rows: 16B-aligned, low-conflict

__global__ void __launch_bounds__(XP_TPB)
xproj_kernel(const float* __restrict__ xg2,
             const float* __restrict__ agg2,
             const float* __restrict__ dinv,
             const float* __restrict__ gcnW, const float* __restrict__ gcnb,
             const float* __restrict__ w_ih,
             const float* __restrict__ b_ih, const float* __restrict__ b_hh,
             float* __restrict__ xproj) {
    __shared__ float s_xg[32 * XG_PITCH];
    __shared__ float s_gw0[32], s_gw1[32], s_gb[32];

    int tid = threadIdx.x;
    if (tid < 32) {
        s_gw0[tid] = gcnW[tid];
        s_gw1[tid] = gcnW[32 + tid];
        s_gb[tid] = gcnb[tid];
    }
    // thread r owns w_ih row r (packed f32x2 pairs) + its bias
    ull wr[16];
    {
        const float* w = w_ih + tid * 32;
#pragma unroll
        for (int j = 0; j < 16; j++) wr[j] = pk(w[2 * j], w[2 * j + 1]);
    }
    float biasr = b_ih[tid] + b_hh[tid];

    int node_base = blockIdx.x * 32;
    int nodeA = tid >> 2;     // 0..31 (phase A)
    int ug = tid & 3;         // u-group of 8
    __syncthreads();

#pragma unroll 1
    for (int t = 0; t < SEQ_LEN; t++) {
        // Phase A: x_gcn tile
        {
            size_t pos = (size_t)(node_base + nodeA) * SEQ_LEN + t;
            float2 xv = *(const float2*)(xg2 + pos * 2);
            float2 av = *(const float2*)(agg2 + pos * 2);
            float di = dinv[pos];
            float d2 = di * di;
            float v0 = fmaf(xv.x, d2, av.x);
            float v1 = fmaf(xv.y, d2, av.y);
#pragma unroll
            for (int k = 0; k < 8; k++) {
                int u = ug * 8 + k;
                s_xg[nodeA * XG_PITCH + u] =
                    fmaxf(fmaf(v0, s_gw0[u], fmaf(v1, s_gw1[u], s_gb[u])), 0.0f);
            }
        }
        __syncthreads();

        // Phase B: thread r -> row r for 32 nodes
        float outv[32];
#pragma unroll 4
        for (int n = 0; n < 32; n++) {
            const ulonglong2* xg = (const ulonglong2*)(s_xg + n * XG_PITCH);
            ull acc0 = 0, acc1 = 0;   // 2 chains for latency
#pragma unroll
            for (int j = 0; j < 8; j++) {
                ulonglong2 v = xg[j];
                acc0 = ffma2(wr[2 * j], v.x, acc0);
                acc1 = ffma2(wr[2 * j + 1], v.y, acc1);
            }
            float2 a = upk(acc0);
            float2 b = upk(acc1);
            outv[n] = a.x + a.y + b.x + b.y + biasr;
        }
        __syncthreads();   // s_xg reads done before next t overwrites

        float4* dst = (float4*)(xproj + (size_t)(t * 128 + tid) * NUM_NODES + node_base);
#pragma unroll
        for (int j = 0; j < 8; j++)
            dst[j] = make_float4(outv[4 * j], outv[4 * j + 1], outv[4 * j + 2], outv[4 * j + 3]);
    }
}

// ---------------------------------------------------------------------------
// LSTM v6: h-GEMM only (x-projection precomputed). 4-way u-split x 2
// nodes/thread, warp-uniform w_hh broadcast from SMEM, c in registers,
// h exchange via padded SMEM. x_proj streamed coalesced (lane = node).
// ---------------------------------------------------------------------------

#define TPB_LSTM 128
#define NODES_PER_BLOCK 64
#define ST_PITCH 34

__global__ void __launch_bounds__(TPB_LSTM)
lstm_kernel(const float* __restrict__ xproj,
            const float* __restrict__ w_hh,
            const float* __restrict__ fcW, const float* __restrict__ fcb,
            float* __restrict__ out) {
    __shared__ __align__(16) float s_wh[4096];
    __shared__ float s_fcw[32];
    __shared__ __align__(16) float s_hx[NODES_PER_BLOCK * ST_PITCH];

    int tid = threadIdx.x;
    for (int i = tid; i < 4096; i += TPB_LSTM) s_wh[i] = w_hh[i];
    if (tid < 32) s_fcw[tid] = fcW[tid];
    for (int i = tid; i < NODES_PER_BLOCK * ST_PITCH; i += TPB_LSTM) s_hx[i] = 0.0f;
    __syncthreads();

    int warp = tid >> 5;           // u-quarter (warp-uniform)
    int lane = tid & 31;
    int ubase = warp * 8;
    int nib0 = lane;
    int nib1 = lane + 32;

    int na0 = blockIdx.x * NODES_PER_BLOCK + nib0;
    int na1 = blockIdx.x * NODES_PER_BLOCK + nib1;
    bool v0ok = na0 < NUM_NODES;
    bool v1ok = na1 < NUM_NODES;
    int n0 = v0ok ? na0 : NUM_NODES - 1;
    int n1 = v1ok ? na1 : NUM_NODES - 1;

    float* hx0 = s_hx + nib0 * ST_PITCH;
    float* hx1 = s_hx + nib1 * ST_PITCH;

    ull h2a[16], h2b[16];
    float c0r[8], c1r[8];
#pragma unroll
    for (int j = 0; j < 16; j++) { h2a[j] = 0ull; h2b[j] = 0ull; }
#pragma unroll
    for (int j = 0; j < 8; j++) { c0r[j] = 0.0f; c1r[j] = 0.0f; }

#pragma unroll 1
    for (int t = 0; t < SEQ_LEN; t++) {
        // stream this step's x_proj values (issued up front; consumed at the
        // end of each uu iteration -> latency mostly hidden by the gemm)
        float xpA[32], xpB[32];   // [gate*8 + uu]
#pragma unroll
        for (int g = 0; g < 4; g++) {
#pragma unroll
            for (int k = 0; k < 8; k++) {
                size_t rb = (size_t)(t * 128 + g * 32 + ubase + k) * NUM_NODES;
                xpA[g * 8 + k] = xproj[rb + n0];
                xpB[g * 8 + k] = xproj[rb + n1];
            }
        }

#pragma unroll
        for (int uu = 0; uu < 8; uu++) {
            int u = ubase + uu;                    // warp-uniform
            const ulonglong2* phi = (const ulonglong2*)(s_wh + u * 32);
            const ulonglong2* phf = (const ulonglong2*)(s_wh + (u + 32) * 32);
            const ulonglong2* phg = (const ulonglong2*)(s_wh + (u + 64) * 32);
            const ulonglong2* pho = (const ulonglong2*)(s_wh + (u + 96) * 32);
            ull ai0 = 0, af0 = 0, ag0 = 0, ao0 = 0;
            ull ai1 = 0, af1 = 0, ag1 = 0, ao1 = 0;
#pragma unroll
            for (int j = 0; j < 8; j++) {
                ulonglong2 w;
                w = phi[j];
                ai0 = ffma2(w.x, h2a[2 * j], ai0); ai0 = ffma2(w.y, h2a[2 * j + 1], ai0);
                ai1 = ffma2(w.x, h2b[2 * j], ai1); ai1 = ffma2(w.y, h2b[2 * j + 1], ai1);
                w = phf[j];
                af0 = ffma2(w.x, h2a[2 * j], af0); af0 = ffma2(w.y, h2a[2 * j + 1], af0);
                af1 = ffma2(w.x, h2b[2 * j], af1); af1 = ffma2(w.y, h2b[2 * j + 1], af1);
                w = phg[j];
                ag0 = ffma2(w.x, h2a[2 * j], ag0); ag0 = ffma2(w.y, h2a[2 * j + 1], ag0);
                ag1 = ffma2(w.x, h2b[2 * j], ag1); ag1 = ffma2(w.y, h2b[2 * j + 1], ag1);
                w = pho[j];
                ao0 = ffma2(w.x, h2a[2 * j], ao0); ao0 = ffma2(w.y, h2a[2 * j + 1], ao0);
                ao1 = ffma2(w.x, h2b[2 * j], ao1); ao1 = ffma2(w.y, h2b[2 * j + 1], ao1);
            }
            {
                float2 vi = upk(ai0), vf = upk(af0), vg = upk(ag0), vo = upk(ao0);
                float gi = sigmoid_hw(vi.x + vi.y + xpA[uu]);
                float gf = sigmoid_hw(vf.x + vf.y + xpA[8 + uu]);
                float gg = tanh_hw(vg.x + vg.y + xpA[16 + uu]);
                float go = sigmoid_hw(vo.x + vo.y + xpA[24 + uu]);
                float c = fmaf(gf, c0r[uu], gi * gg);
                c0r[uu] = c;
                hx0[u] = go * tanh_hw(c);
            }
            {
                float2 vi = upk(ai1), vf = upk(af1), vg = upk(ag1), vo = upk(ao1);
                float gi = sigmoid_hw(vi.x + vi.y + xpB[uu]);
                float gf = sigmoid_hw(vf.x + vf.y + xpB[8 + uu]);
                float gg = tanh_hw(vg.x + vg.y + xpB[16 + uu]);
                float go = sigmoid_hw(vo.x + vo.y + xpB[24 + uu]);
                float c = fmaf(gf, c1r[uu], gi * gg);
                c1r[uu] = c;
                hx1[u] = go * tanh_hw(c);
            }
        }

        __syncthreads();
#pragma unroll
        for (int j = 0; j < 16; j++) {
            h2a[j] = *(const ull*)(hx0 + 2 * j);
            h2b[j] = *(const ull*)(hx1 + 2 * j);
        }
        __syncthreads();
    }

    if (warp == 0) {
        float acc0 = fcb[0], acc1 = fcb[0];
#pragma unroll
        for (int j = 0; j < 16; j++) {
            float2 ha = upk(h2a[j]);
            float2 hb = upk(h2b[j]);
            acc0 = fmaf(ha.x, s_fcw[2 * j], acc0);
            acc0 = fmaf(ha.y, s_fcw[2 * j + 1], acc0);
            acc1 = fmaf(hb.x, s_fcw[2 * j], acc1);
            acc1 = fmaf(hb.y, s_fcw[2 * j + 1], acc1);
        }
        if (v0ok) out[na0] = acc0;
        if (v1ok) out[na1] = acc1;
    }
}

// ---------------------------------------------------------------------------

extern "C" void kernel_launch(void* const* d_in, const int* in_sizes, int n_in,
                              void* d_out, int out_size) {
    const float* x = (const float*)d_in[0];
    const int* ei = (const int*)d_in[1];
    const float* gcnW = (const float*)d_in[2];
    const float* gcnb = (const float*)d_in[3];
    const float* w_ih = (const float*)d_in[4];
    const float* w_hh = (const float*)d_in[5];
    const float* b_ih = (const float*)d_in[6];
    const float* b_hh = (const float*)d_in[7];
    const float* fcW = (const float*)d_in[8];
    const float* fcb = (const float*)d_in[9];
    float* out = (float*)d_out;

    void* aggp = nullptr;
    void* degp = nullptr;
    void* xpp = nullptr;
    cudaGetSymbolAddress(&aggp, g_agg2);
    cudaGetSymbolAddress(&degp, g_deg);
    cudaGetSymbolAddress(&xpp, g_xproj);

    cudaMemsetAsync(aggp, 0, sizeof(float) * (size_t)N_TOTAL * 2);
    cudaMemsetAsync(degp, 0, sizeof(float) * (size_t)N_TOTAL);

    deg_kernel<<<(N_EDGES + 255) / 256, 256>>>(ei, (float*)degp);
    dinv_kernel<<<(N_TOTAL + 255) / 256, 256>>>((float*)degp);
    edge_scatter2<<<(N_EDGES + 255) / 256, 256>>>(ei, x, (const float*)degp, (float*)aggp);

    xproj_kernel<<<NUM_NODES / 32, XP_TPB>>>(
        x, (const float*)aggp, (const float*)degp, gcnW, gcnb,
        w_ih, b_ih, b_hh, (float*)xpp);

    int lstm_blocks = (NUM_NODES + NODES_PER_BLOCK - 1) / NODES_PER_BLOCK;  // 313
    lstm_kernel<<<lstm_blocks, TPB_LSTM>>>(
        (const float*)xpp, w_hh, fcW, fcb, out);
}

// round 14
// speedup vs baseline: 1.5294x; 1.5294x over previous
#include <cuda_runtime.h>
#include <cuda_bf16.h>
#include <cstdint>

#define NUM_NODES 20000
#define SEQ_LEN 128
#define HIDDEN 32
#define N_TOTAL (NUM_NODES * SEQ_LEN)        // 2,560,000
#define N_EDGES 2000000

__device__ float g_agg2[(size_t)N_TOTAL * 2];
__device__ float g_deg[N_TOTAL];

typedef unsigned long long ull;

__device__ __forceinline__ ull ffma2(ull a, ull b, ull c) {
    ull d;
    asm("fma.rn.f32x2 %0, %1, %2, %3;" : "=l"(d) : "l"(a), "l"(b), "l"(c));
    return d;
}
__device__ __forceinline__ ull pk(float lo, float hi) {
    ull r;
    asm("mov.b64 %0, {%1, %2};" : "=l"(r) : "f"(lo), "f"(hi));
    return r;
}
__device__ __forceinline__ float2 upk(ull v) {
    float2 r;
    asm("mov.b64 {%0, %1}, %2;" : "=f"(r.x), "=f"(r.y) : "l"(v));
    return r;
}
__device__ __forceinline__ float tanh_hw(float v) {
    float r;
    asm("tanh.approx.f32 %0, %1;" : "=f"(r) : "f"(v));
    return r;
}
__device__ __forceinline__ float sigmoid_hw(float v) {
    return fmaf(0.5f, tanh_hw(0.5f * v), 0.5f);
}

// ---------------------------------------------------------------------------
// GCN kernels (edge_index arrives as int32)
// ---------------------------------------------------------------------------

__global__ void deg_kernel(const int* __restrict__ ei, float* __restrict__ deg) {
    int e = blockIdx.x * blockDim.x + threadIdx.x;
    if (e < N_EDGES) {
        int dst = ei[N_EDGES + e];
        atomicAdd(deg + dst, 1.0f);
    }
}

__global__ void dinv_kernel(float* __restrict__ deg) {
    int i = blockIdx.x * blockDim.x + threadIdx.x;
    if (i < N_TOTAL) {
        deg[i] = rsqrtf(deg[i] + 1.0f);
    }
}

__global__ void edge_scatter2(const int* __restrict__ ei,
                              const float* __restrict__ x,
                              const float* __restrict__ dinv,
                              float* __restrict__ agg2) {
    int e = blockIdx.x * blockDim.x + threadIdx.x;
    if (e >= N_EDGES) return;
    int src = ei[e];
    int dst = ei[N_EDGES + e];
    float norm = dinv[src] * dinv[dst];
    float2 xv = *(const float2*)(x + 2 * (size_t)src);
    float* p = agg2 + 2 * (size_t)dst;
    atomicAdd(p, xv.x * norm);
    atomicAdd(p + 1, xv.y * norm);
}

// ---------------------------------------------------------------------------
// LSTM v7: fused (R10 structure), 4-way u-split x 1 node/thread.
// Block = 128 threads = 4 warps over the SAME 32 nodes; warp w computes
// u-rows [8w, 8w+8) for all 32 nodes (lane = node). ~140 regs/thread ->
// 3 blocks/SM -> 3 warps/SMSP for latency hiding. Weight LDS.128 broadcasts,
// c in registers, h exchange via padded SMEM, MUFU.TANH gates, fused FC.
// ---------------------------------------------------------------------------

#define TPB_LSTM 128
#define NODES_PER_BLOCK 32
#define ST_PITCH 34          // even pitch -> 8B-aligned rows, conflict-free

__global__ void __launch_bounds__(TPB_LSTM)
lstm_kernel(const float* __restrict__ xg2,
            const float* __restrict__ agg2,
            const float* __restrict__ dinv,
            const float* __restrict__ gcnW, const float* __restrict__ gcnb,
            const float* __restrict__ w_ih, const float* __restrict__ w_hh,
            const float* __restrict__ b_ih, const float* __restrict__ b_hh,
            const float* __restrict__ fcW, const float* __restrict__ fcb,
            float* __restrict__ out) {
    __shared__ __align__(16) float s_wi[4096];
    __shared__ __align__(16) float s_wh[4096];
    __shared__ float s_bias[128];
    __shared__ float s_fcw[32];
    __shared__ float s_gw0[32];
    __shared__ float s_gw1[32];
    __shared__ float s_gb[32];
    __shared__ __align__(16) float s_hx[NODES_PER_BLOCK * ST_PITCH];

    int tid = threadIdx.x;
    for (int i = tid; i < 4096; i += TPB_LSTM) {
        s_wi[i] = w_ih[i];
        s_wh[i] = w_hh[i];
    }
    if (tid < 128) s_bias[tid] = b_ih[tid] + b_hh[tid];
    if (tid < 32) {
        s_fcw[tid] = fcW[tid];
        s_gw0[tid] = gcnW[tid];
        s_gw1[tid] = gcnW[32 + tid];
        s_gb[tid] = gcnb[tid];
    }
    for (int i = tid; i < NODES_PER_BLOCK * ST_PITCH; i += TPB_LSTM) s_hx[i] = 0.0f;
    __syncthreads();

    int warp = tid >> 5;           // 0..3 = u-quarter (warp-uniform)
    int lane = tid & 31;           // node within block
    int ubase = warp * 8;

    int na0 = blockIdx.x * NODES_PER_BLOCK + lane;
    bool v0ok = na0 < NUM_NODES;
    int n0 = v0ok ? na0 : NUM_NODES - 1;

    const float2* xp0 = (const float2*)(xg2 + (size_t)n0 * SEQ_LEN * 2);
    const float2* ap0 = (const float2*)(agg2 + (size_t)n0 * SEQ_LEN * 2);
    const float* dp0 = dinv + (size_t)n0 * SEQ_LEN;

    float* hx0 = s_hx + lane * ST_PITCH;

    ull x2a[16], h2a[16];
    float c0r[8];
#pragma unroll
    for (int j = 0; j < 16; j++) h2a[j] = 0ull;
#pragma unroll
    for (int j = 0; j < 8; j++) c0r[j] = 0.0f;

    float2 nx0 = xp0[0], nav0 = ap0[0];
    float nd0 = dp0[0];

#pragma unroll 1
    for (int t = 0; t < SEQ_LEN; t++) {
        float2 xv0 = nx0, av0 = nav0;
        float di0 = nd0;
        int tn = t + 1 < SEQ_LEN ? t + 1 : t;
        nx0 = xp0[tn]; nav0 = ap0[tn]; nd0 = dp0[tn];

        // fused GCN finalize
        float d20 = di0 * di0;
        float p0 = fmaf(xv0.x, d20, av0.x), p1 = fmaf(xv0.y, d20, av0.y);
#pragma unroll
        for (int j = 0; j < 16; j++) {
            float ga = fmaxf(fmaf(p0, s_gw0[2 * j], fmaf(p1, s_gw1[2 * j], s_gb[2 * j])), 0.0f);
            float gb_ = fmaxf(fmaf(p0, s_gw0[2 * j + 1], fmaf(p1, s_gw1[2 * j + 1], s_gb[2 * j + 1])), 0.0f);
            x2a[j] = pk(ga, gb_);
        }

#pragma unroll
        for (int uu = 0; uu < 8; uu++) {
            int u = ubase + uu;                    // warp-uniform
            const ulonglong2* pxi = (const ulonglong2*)(s_wi + u * 32);
            const ulonglong2* pxf = (const ulonglong2*)(s_wi + (u + 32) * 32);
            const ulonglong2* pxg = (const ulonglong2*)(s_wi + (u + 64) * 32);
            const ulonglong2* pxo = (const ulonglong2*)(s_wi + (u + 96) * 32);
            const ulonglong2* phi = (const ulonglong2*)(s_wh + u * 32);
            const ulonglong2* phf = (const ulonglong2*)(s_wh + (u + 32) * 32);
            const ulonglong2* phg = (const ulonglong2*)(s_wh + (u + 64) * 32);
            const ulonglong2* pho = (const ulonglong2*)(s_wh + (u + 96) * 32);
            ull ai0 = 0, af0 = 0, ag0 = 0, ao0 = 0;
#pragma unroll
            for (int j = 0; j < 8; j++) {
                ulonglong2 w;
                w = pxi[j];
                ai0 = ffma2(w.x, x2a[2 * j], ai0); ai0 = ffma2(w.y, x2a[2 * j + 1], ai0);
                w = pxf[j];
                af0 = ffma2(w.x, x2a[2 * j], af0); af0 = ffma2(w.y, x2a[2 * j + 1], af0);
                w = pxg[j];
                ag0 = ffma2(w.x, x2a[2 * j], ag0); ag0 = ffma2(w.y, x2a[2 * j + 1], ag0);
                w = pxo[j];
                ao0 = ffma2(w.x, x2a[2 * j], ao0); ao0 = ffma2(w.y, x2a[2 * j + 1], ao0);
                w = phi[j];
                ai0 = ffma2(w.x, h2a[2 * j], ai0); ai0 = ffma2(w.y, h2a[2 * j + 1], ai0);
                w = phf[j];
                af0 = ffma2(w.x, h2a[2 * j], af0); af0 = ffma2(w.y, h2a[2 * j + 1], af0);
                w = phg[j];
                ag0 = ffma2(w.x, h2a[2 * j], ag0); ag0 = ffma2(w.y, h2a[2 * j + 1], ag0);
                w = pho[j];
                ao0 = ffma2(w.x, h2a[2 * j], ao0); ao0 = ffma2(w.y, h2a[2 * j + 1], ao0);
            }
            float2 vi = upk(ai0), vf = upk(af0), vg = upk(ag0), vo = upk(ao0);
            float gi = sigmoid_hw(vi.x + vi.y + s_bias[u]);
            float gf = sigmoid_hw(vf.x + vf.y + s_bias[32 + u]);
            float gg = tanh_hw(vg.x + vg.y + s_bias[64 + u]);
            float go = sigmoid_hw(vo.x + vo.y + s_bias[96 + u]);
            float c = fmaf(gf, c0r[uu], gi * gg);
            c0r[uu] = c;
            hx0[u] = go * tanh_hw(c);
        }

        __syncthreads();   // all 4 warps published their u-quarters
#pragma unroll
        for (int j = 0; j < 16; j++) h2a[j] = *(const ull*)(hx0 + 2 * j);
        __syncthreads();   // reads done before next-step writes
    }

    if (warp == 0 && v0ok) {
        float acc0 = fcb[0];
#pragma unroll
        for (int j = 0; j < 16; j++) {
            float2 ha = upk(h2a[j]);
            acc0 = fmaf(ha.x, s_fcw[2 * j], acc0);
            acc0 = fmaf(ha.y, s_fcw[2 * j + 1], acc0);
        }
        out[na0] = acc0;
    }
}

// ---------------------------------------------------------------------------

extern "C" void kernel_launch(void* const* d_in, const int* in_sizes, int n_in,
                              void* d_out, int out_size) {
    const float* x = (const float*)d_in[0];
    const int* ei = (const int*)d_in[1];
    const float* gcnW = (const float*)d_in[2];
    const float* gcnb = (const float*)d_in[3];
    const float* w_ih = (const float*)d_in[4];
    const float* w_hh = (const float*)d_in[5];
    const float* b_ih = (const float*)d_in[6];
    const float* b_hh = (const float*)d_in[7];
    const float* fcW = (const float*)d_in[8];
    const float* fcb = (const float*)d_in[9];
    float* out = (float*)d_out;

    void* aggp = nullptr;
    void* degp = nullptr;
    cudaGetSymbolAddress(&aggp, g_agg2);
    cudaGetSymbolAddress(&degp, g_deg);

    cudaMemsetAsync(aggp, 0, sizeof(float) * (size_t)N_TOTAL * 2);
    cudaMemsetAsync(degp, 0, sizeof(float) * (size_t)N_TOTAL);

    deg_kernel<<<(N_EDGES + 255) / 256, 256>>>(ei, (float*)degp);
    dinv_kernel<<<(N_TOTAL + 255) / 256, 256>>>((float*)degp);
    edge_scatter2<<<(N_EDGES + 255) / 256, 256>>>(ei, x, (const float*)degp, (float*)aggp);

    int lstm_blocks = (NUM_NODES + NODES_PER_BLOCK - 1) / NODES_PER_BLOCK;  // 625
    lstm_kernel<<<lstm_blocks, TPB_LSTM>>>(
        x, (const float*)aggp, (const float*)degp, gcnW, gcnb,
        w_ih, w_hh, b_ih, b_hh, fcW, fcb, out);
}

// round 16
// speedup vs baseline: 1.5310x; 1.0011x over previous
#include <cuda_runtime.h>
#include <cuda_bf16.h>
#include <cstdint>

#define NUM_NODES 20000
#define SEQ_LEN 128
#define HIDDEN 32
#define N_TOTAL (NUM_NODES * SEQ_LEN)        // 2,560,000
#define N_EDGES 2000000

__device__ float g_agg2[(size_t)N_TOTAL * 2];
__device__ float g_deg[N_TOTAL];

typedef unsigned long long ull;

__device__ __forceinline__ ull ffma2(ull a, ull b, ull c) {
    ull d;
    asm("fma.rn.f32x2 %0, %1, %2, %3;" : "=l"(d) : "l"(a), "l"(b), "l"(c));
    return d;
}
__device__ __forceinline__ ull pk(float lo, float hi) {
    ull r;
    asm("mov.b64 %0, {%1, %2};" : "=l"(r) : "f"(lo), "f"(hi));
    return r;
}
__device__ __forceinline__ float2 upk(ull v) {
    float2 r;
    asm("mov.b64 {%0, %1}, %2;" : "=f"(r.x), "=f"(r.y) : "l"(v));
    return r;
}
__device__ __forceinline__ float tanh_hw(float v) {
    float r;
    asm("tanh.approx.f32 %0, %1;" : "=f"(r) : "f"(v));
    return r;
}
__device__ __forceinline__ float sigmoid_hw(float v) {
    return fmaf(0.5f, tanh_hw(0.5f * v), 0.5f);
}

// ---------------------------------------------------------------------------
// GCN kernels (edge_index arrives as int32)
// ---------------------------------------------------------------------------

__global__ void deg_kernel(const int* __restrict__ ei, float* __restrict__ deg) {
    int e = blockIdx.x * blockDim.x + threadIdx.x;
    if (e < N_EDGES) {
        int dst = ei[N_EDGES + e];
        atomicAdd(deg + dst, 1.0f);
    }
}

__global__ void dinv_kernel(float* __restrict__ deg) {
    int i = blockIdx.x * blockDim.x + threadIdx.x;
    if (i < N_TOTAL) {
        deg[i] = rsqrtf(deg[i] + 1.0f);
    }
}

__global__ void edge_scatter2(const int* __restrict__ ei,
                              const float* __restrict__ x,
                              const float* __restrict__ dinv,
                              float* __restrict__ agg2) {
    int e = blockIdx.x * blockDim.x + threadIdx.x;
    if (e >= N_EDGES) return;
    int src = ei[e];
    int dst = ei[N_EDGES + e];
    float norm = dinv[src] * dinv[dst];
    float2 xv = *(const float2*)(x + 2 * (size_t)src);
    float* p = agg2 + 2 * (size_t)dst;
    atomicAdd(p, xv.x * norm);
    atomicAdd(p + 1, xv.y * norm);
}

// ---------------------------------------------------------------------------
// LSTM v7: fused (R10 structure), 4-way u-split x 1 node/thread.
// Block = 128 threads = 4 warps over the SAME 32 nodes; warp w computes
// u-rows [8w, 8w+8) for all 32 nodes (lane = node). ~140 regs/thread ->
// 3 blocks/SM -> 3 warps/SMSP for latency hiding. Weight LDS.128 broadcasts,
// c in registers, h exchange via padded SMEM, MUFU.TANH gates, fused FC.
// ---------------------------------------------------------------------------

#define TPB_LSTM 128
#define NODES_PER_BLOCK 32
#define ST_PITCH 34          // even pitch -> 8B-aligned rows, conflict-free

__global__ void __launch_bounds__(TPB_LSTM)
lstm_kernel(const float* __restrict__ xg2,
            const float* __restrict__ agg2,
            const float* __restrict__ dinv,
            const float* __restrict__ gcnW, const float* __restrict__ gcnb,
            const float* __restrict__ w_ih, const float* __restrict__ w_hh,
            const float* __restrict__ b_ih, const float* __restrict__ b_hh,
            const float* __restrict__ fcW, const float* __restrict__ fcb,
            float* __restrict__ out) {
    __shared__ __align__(16) float s_wi[4096];
    __shared__ __align__(16) float s_wh[4096];
    __shared__ float s_bias[128];
    __shared__ float s_fcw[32];
    __shared__ float s_gw0[32];
    __shared__ float s_gw1[32];
    __shared__ float s_gb[32];
    __shared__ __align__(16) float s_hx[NODES_PER_BLOCK * ST_PITCH];

    int tid = threadIdx.x;
    for (int i = tid; i < 4096; i += TPB_LSTM) {
        s_wi[i] = w_ih[i];
        s_wh[i] = w_hh[i];
    }
    if (tid < 128) s_bias[tid] = b_ih[tid] + b_hh[tid];
    if (tid < 32) {
        s_fcw[tid] = fcW[tid];
        s_gw0[tid] = gcnW[tid];
        s_gw1[tid] = gcnW[32 + tid];
        s_gb[tid] = gcnb[tid];
    }
    for (int i = tid; i < NODES_PER_BLOCK * ST_PITCH; i += TPB_LSTM) s_hx[i] = 0.0f;
    __syncthreads();

    int warp = tid >> 5;           // 0..3 = u-quarter (warp-uniform)
    int lane = tid & 31;           // node within block
    int ubase = warp * 8;

    int na0 = blockIdx.x * NODES_PER_BLOCK + lane;
    bool v0ok = na0 < NUM_NODES;
    int n0 = v0ok ? na0 : NUM_NODES - 1;

    const float2* xp0 = (const float2*)(xg2 + (size_t)n0 * SEQ_LEN * 2);
    const float2* ap0 = (const float2*)(agg2 + (size_t)n0 * SEQ_LEN * 2);
    const float* dp0 = dinv + (size_t)n0 * SEQ_LEN;

    float* hx0 = s_hx + lane * ST_PITCH;

    ull x2a[16], h2a[16];
    float c0r[8];
#pragma unroll
    for (int j = 0; j < 16; j++) h2a[j] = 0ull;
#pragma unroll
    for (int j = 0; j < 8; j++) c0r[j] = 0.0f;

    float2 nx0 = xp0[0], nav0 = ap0[0];
    float nd0 = dp0[0];

#pragma unroll 1
    for (int t = 0; t < SEQ_LEN; t++) {
        float2 xv0 = nx0, av0 = nav0;
        float di0 = nd0;
        int tn = t + 1 < SEQ_LEN ? t + 1 : t;
        nx0 = xp0[tn]; nav0 = ap0[tn]; nd0 = dp0[tn];

        // fused GCN finalize
        float d20 = di0 * di0;
        float p0 = fmaf(xv0.x, d20, av0.x), p1 = fmaf(xv0.y, d20, av0.y);
#pragma unroll
        for (int j = 0; j < 16; j++) {
            float ga = fmaxf(fmaf(p0, s_gw0[2 * j], fmaf(p1, s_gw1[2 * j], s_gb[2 * j])), 0.0f);
            float gb_ = fmaxf(fmaf(p0, s_gw0[2 * j + 1], fmaf(p1, s_gw1[2 * j + 1], s_gb[2 * j + 1])), 0.0f);
            x2a[j] = pk(ga, gb_);
        }

#pragma unroll
        for (int uu = 0; uu < 8; uu++) {
            int u = ubase + uu;                    // warp-uniform
            const ulonglong2* pxi = (const ulonglong2*)(s_wi + u * 32);
            const ulonglong2* pxf = (const ulonglong2*)(s_wi + (u + 32) * 32);
            const ulonglong2* pxg = (const ulonglong2*)(s_wi + (u + 64) * 32);
            const ulonglong2* pxo = (const ulonglong2*)(s_wi + (u + 96) * 32);
            const ulonglong2* phi = (const ulonglong2*)(s_wh + u * 32);
            const ulonglong2* phf = (const ulonglong2*)(s_wh + (u + 32) * 32);
            const ulonglong2* phg = (const ulonglong2*)(s_wh + (u + 64) * 32);
            const ulonglong2* pho = (const ulonglong2*)(s_wh + (u + 96) * 32);
            ull ai0 = 0, af0 = 0, ag0 = 0, ao0 = 0;
#pragma unroll
            for (int j = 0; j < 8; j++) {
                ulonglong2 w;
                w = pxi[j];
                ai0 = ffma2(w.x, x2a[2 * j], ai0); ai0 = ffma2(w.y, x2a[2 * j + 1], ai0);
                w = pxf[j];
                af0 = ffma2(w.x, x2a[2 * j], af0); af0 = ffma2(w.y, x2a[2 * j + 1], af0);
                w = pxg[j];
                ag0 = ffma2(w.x, x2a[2 * j], ag0); ag0 = ffma2(w.y, x2a[2 * j + 1], ag0);
                w = pxo[j];
                ao0 = ffma2(w.x, x2a[2 * j], ao0); ao0 = ffma2(w.y, x2a[2 * j + 1], ao0);
                w = phi[j];
                ai0 = ffma2(w.x, h2a[2 * j], ai0); ai0 = ffma2(w.y, h2a[2 * j + 1], ai0);
                w = phf[j];
                af0 = ffma2(w.x, h2a[2 * j], af0); af0 = ffma2(w.y, h2a[2 * j + 1], af0);
                w = phg[j];
                ag0 = ffma2(w.x, h2a[2 * j], ag0); ag0 = ffma2(w.y, h2a[2 * j + 1], ag0);
                w = pho[j];
                ao0 = ffma2(w.x, h2a[2 * j], ao0); ao0 = ffma2(w.y, h2a[2 * j + 1], ao0);
            }
            float2 vi = upk(ai0), vf = upk(af0), vg = upk(ag0), vo = upk(ao0);
            float gi = sigmoid_hw(vi.x + vi.y + s_bias[u]);
            float gf = sigmoid_hw(vf.x + vf.y + s_bias[32 + u]);
            float gg = tanh_hw(vg.x + vg.y + s_bias[64 + u]);
            float go = sigmoid_hw(vo.x + vo.y + s_bias[96 + u]);
            float c = fmaf(gf, c0r[uu], gi * gg);
            c0r[uu] = c;
            hx0[u] = go * tanh_hw(c);
        }

        __syncthreads();   // all 4 warps published their u-quarters
#pragma unroll
        for (int j = 0; j < 16; j++) h2a[j] = *(const ull*)(hx0 + 2 * j);
        __syncthreads();   // reads done before next-step writes
    }

    if (warp == 0 && v0ok) {
        float acc0 = fcb[0];
#pragma unroll
        for (int j = 0; j < 16; j++) {
            float2 ha = upk(h2a[j]);
            acc0 = fmaf(ha.x, s_fcw[2 * j], acc0);
            acc0 = fmaf(ha.y, s_fcw[2 * j + 1], acc0);
        }
        out[na0] = acc0;
    }
}

// ---------------------------------------------------------------------------

extern "C" void kernel_launch(void* const* d_in, const int* in_sizes, int n_in,
                              void* d_out, int out_size) {
    const float* x = (const float*)d_in[0];
    const int* ei = (const int*)d_in[1];
    const float* gcnW = (const float*)d_in[2];
    const float* gcnb = (const float*)d_in[3];
    const float* w_ih = (const float*)d_in[4];
    const float* w_hh = (const float*)d_in[5];
    const float* b_ih = (const float*)d_in[6];
    const float* b_hh = (const float*)d_in[7];
    const float* fcW = (const float*)d_in[8];
    const float* fcb = (const float*)d_in[9];
    float* out = (float*)d_out;

    void* aggp = nullptr;
    void* degp = nullptr;
    cudaGetSymbolAddress(&aggp, g_agg2);
    cudaGetSymbolAddress(&degp, g_deg);

    cudaMemsetAsync(aggp, 0, sizeof(float) * (size_t)N_TOTAL * 2);
    cudaMemsetAsync(degp, 0, sizeof(float) * (size_t)N_TOTAL);

    deg_kernel<<<(N_EDGES + 255) / 256, 256>>>(ei, (float*)degp);
    dinv_kernel<<<(N_TOTAL + 255) / 256, 256>>>((float*)degp);
    edge_scatter2<<<(N_EDGES + 255) / 256, 256>>>(ei, x, (const float*)degp, (float*)aggp);

    int lstm_blocks = (NUM_NODES + NODES_PER_BLOCK - 1) / NODES_PER_BLOCK;  // 625
    lstm_kernel<<<lstm_blocks, TPB_LSTM>>>(
        x, (const float*)aggp, (const float*)degp, gcnW, gcnb,
        w_ih, w_hh, b_ih, b_hh, fcW, fcb, out);
}